// round 14
// baseline (speedup 1.0000x reference)
#include <cuda_runtime.h>
#include <cuda_fp16.h>
#include <cstdint>

// ---------------- problem constants ----------------
#define BATCH 16
#define L2TAPS 225
#define FCDIM  2048
#define HIN 128
#define WIN 128
#define HU 256
#define WU 256
#define OC1 64
#define W1OUT (OC1*81)

// ---------------- device scratch ----------------
__device__ float g_kfc[BATCH*FCDIM];
__device__ float g_w1 [BATCH*W1OUT];
__device__ float g_up [BATCH*HU*WU];
__device__ unsigned short g_f1h[(size_t)BATCH*HU*WU*64];   // channels-last fp16
__device__ float g_f2 [(size_t)BATCH*OC1*HU*WU];           // planar f32

// ---------------- helpers ----------------
__device__ __forceinline__ uint32_t smem_u32(const void* p) {
    uint32_t a;
    asm("{ .reg .u64 t; cvta.to.shared.u64 t, %1; cvt.u32.u64 %0, t; }" : "=r"(a) : "l"(p));
    return a;
}
__device__ __forceinline__ unsigned short f2h(float v) {
    __half h = __float2half_rn(v);
    return *reinterpret_cast<unsigned short*>(&h);
}

__device__ __forceinline__ void ldsm_x4(uint32_t* r, uint32_t addr) {
    asm volatile("ldmatrix.sync.aligned.m8n8.x4.shared.b16 {%0,%1,%2,%3}, [%4];"
        : "=r"(r[0]), "=r"(r[1]), "=r"(r[2]), "=r"(r[3]) : "r"(addr));
}
__device__ __forceinline__ void ldsm_x2t(uint32_t* r, uint32_t addr) {
    asm volatile("ldmatrix.sync.aligned.m8n8.x2.trans.shared.b16 {%0,%1}, [%2];"
        : "=r"(r[0]), "=r"(r[1]) : "r"(addr));
}
__device__ __forceinline__ void mma16816h(float* c, const uint32_t* a, const uint32_t* b) {
    asm volatile("mma.sync.aligned.m16n8k16.row.col.f32.f16.f16.f32 "
        "{%0,%1,%2,%3}, {%4,%5,%6,%7}, {%8,%9}, {%0,%1,%2,%3};"
        : "+f"(c[0]), "+f"(c[1]), "+f"(c[2]), "+f"(c[3])
        : "r"(a[0]), "r"(a[1]), "r"(a[2]), "r"(a[3]), "r"(b[0]), "r"(b[1]));
}
__device__ __forceinline__ void cp16(uint32_t daddr, const void* src, int szbytes) {
    asm volatile("cp.async.cg.shared.global [%0], [%1], 16, %2;"
        :: "r"(daddr), "l"(src), "r"(szbytes) : "memory");
}
#define CP_COMMIT() asm volatile("cp.async.commit_group;" ::: "memory")
#define CP_WAIT1()  asm volatile("cp.async.wait_group 1;" ::: "memory")

// ---------------- kernel 1: kfc = relu(kflat @ kl_w^T + kl_b) ----------------
__global__ void k_kfc(const float* __restrict__ kern,
                      const float* __restrict__ kl_w,
                      const float* __restrict__ kl_b) {
    __shared__ float sk[L2TAPS];
    int b = blockIdx.x;
    for (int i = threadIdx.x; i < L2TAPS; i += blockDim.x)
        sk[i] = kern[b*L2TAPS + i];
    __syncthreads();
    for (int j = threadIdx.x; j < FCDIM; j += blockDim.x) {
        float acc = kl_b[j];
        const float* w = kl_w + (size_t)j*L2TAPS;
        #pragma unroll 5
        for (int i = 0; i < L2TAPS; i++) acc = fmaf(sk[i], w[i], acc);
        g_kfc[b*FCDIM + j] = fmaxf(acc, 0.0f);
    }
}

// ---------------- kernel 2: w1 = kfc @ w1_w^T + w1_b ----------------
__global__ void k_w1(const float* __restrict__ w1w,
                     const float* __restrict__ w1b) {
    __shared__ float sx[32*17];
    __shared__ float sw[32*65];
    int o0 = blockIdx.x * 64;
    int o  = threadIdx.x & 63;
    int bq = threadIdx.x >> 6;
    float acc[4] = {0.f, 0.f, 0.f, 0.f};
    for (int k0 = 0; k0 < FCDIM; k0 += 32) {
        for (int idx = threadIdx.x; idx < 64*32; idx += 256) {
            int ro = idx >> 5, ck = idx & 31;
            sw[ck*65 + ro] = w1w[(size_t)(o0 + ro)*FCDIM + k0 + ck];
        }
        for (int idx = threadIdx.x; idx < 16*32; idx += 256) {
            int rb = idx >> 5, ck = idx & 31;
            sx[ck*17 + rb] = g_kfc[rb*FCDIM + k0 + ck];
        }
        __syncthreads();
        #pragma unroll
        for (int k = 0; k < 32; k++) {
            float wv = sw[k*65 + o];
            acc[0] = fmaf(wv, sx[k*17 + bq     ], acc[0]);
            acc[1] = fmaf(wv, sx[k*17 + bq +  4], acc[1]);
            acc[2] = fmaf(wv, sx[k*17 + bq +  8], acc[2]);
            acc[3] = fmaf(wv, sx[k*17 + bq + 12], acc[3]);
        }
        __syncthreads();
    }
    float bias = w1b[o0 + o];
    #pragma unroll
    for (int i = 0; i < 4; i++)
        g_w1[(bq + 4*i)*W1OUT + o0 + o] = acc[i] + bias;
}

// ---------------- kernel 3: bilinear x2 upsample ----------------
__global__ void k_up(const float* __restrict__ img) {
    int idx = blockIdx.x*blockDim.x + threadIdx.x;
    if (idx >= BATCH*HU*WU) return;
    int x = idx & 255, y = (idx >> 8) & 255, b = idx >> 16;
    float syf = y*0.5f - 0.25f;
    float sxf = x*0.5f - 0.25f;
    int y0 = (int)floorf(syf); float wy = syf - (float)y0;
    int x0 = (int)floorf(sxf); float wx = sxf - (float)x0;
    int y0c = max(y0, 0), y1c = min(y0+1, HIN-1);
    int x0c = max(x0, 0), x1c = min(x0+1, WIN-1);
    const float* p = img + (size_t)b*HIN*WIN;
    float v00 = p[y0c*WIN + x0c], v01 = p[y0c*WIN + x1c];
    float v10 = p[y1c*WIN + x0c], v11 = p[y1c*WIN + x1c];
    g_up[idx] = (1.f-wy)*((1.f-wx)*v00 + wx*v01) + wy*((1.f-wx)*v10 + wx*v11);
}

// ---------------- kernel 5: per-sample conv 9x9, 1->64, relu ----------------
// writes channels-last fp16 (hi only)
__global__ __launch_bounds__(256, 2)
void k_conv1() {
    __shared__ float sx[40*40];
    __shared__ float sw[8*81];
    int b   = blockIdx.z >> 3;
    int ocg = blockIdx.z & 7;
    int gx0 = blockIdx.x*32 - 4;
    int gy0 = blockIdx.y*32 - 4;
    int tx = threadIdx.x & 15, ty = threadIdx.x >> 4;

    const float* src = g_up + (size_t)b*HU*WU;
    for (int idx = threadIdx.x; idx < 40*40; idx += 256) {
        int r = idx / 40, c = idx - r*40;
        int gy = gy0 + r, gx = gx0 + c;
        sx[idx] = (gy >= 0 && gy < HU && gx >= 0 && gx < WU)
                  ? src[gy*WU + gx] : 0.f;
    }
    const float* wsrc = g_w1 + b*W1OUT + ocg*8*81;
    for (int idx = threadIdx.x; idx < 8*81; idx += 256) sw[idx] = wsrc[idx];
    __syncthreads();

    float acc[8][4];
    #pragma unroll
    for (int o = 0; o < 8; o++)
        #pragma unroll
        for (int i = 0; i < 4; i++) acc[o][i] = 0.f;

    int bx = 2*tx, by = 2*ty;
    for (int dy = 0; dy < 9; dy++) {
        #pragma unroll
        for (int dx = 0; dx < 9; dx++) {
            float xv0 = sx[(by+dy)*40 + bx+dx];
            float xv1 = sx[(by+dy)*40 + bx+dx+1];
            float xv2 = sx[(by+dy+1)*40 + bx+dx];
            float xv3 = sx[(by+dy+1)*40 + bx+dx+1];
            #pragma unroll
            for (int o = 0; o < 8; o++) {
                float wv = sw[o*81 + dy*9 + dx];
                acc[o][0] = fmaf(wv, xv0, acc[o][0]);
                acc[o][1] = fmaf(wv, xv1, acc[o][1]);
                acc[o][2] = fmaf(wv, xv2, acc[o][2]);
                acc[o][3] = fmaf(wv, xv3, acc[o][3]);
            }
        }
    }

    #pragma unroll
    for (int i = 0; i < 4; i++) {
        int yy = blockIdx.y*32 + by + (i >> 1);
        int xx = blockIdx.x*32 + bx + (i & 1);
        size_t base = ((size_t)(b*65536 + yy*256 + xx))*64 + ocg*8;
        unsigned short hs[8];
        #pragma unroll
        for (int o = 0; o < 8; o++)
            hs[o] = f2h(fmaxf(acc[o][i], 0.f));
        uint4 uh;
        uh.x = (uint32_t)hs[0] | ((uint32_t)hs[1] << 16);
        uh.y = (uint32_t)hs[2] | ((uint32_t)hs[3] << 16);
        uh.z = (uint32_t)hs[4] | ((uint32_t)hs[5] << 16);
        uh.w = (uint32_t)hs[6] | ((uint32_t)hs[7] << 16);
        *reinterpret_cast<uint4*>(g_f1h + base) = uh;
    }
}

// ---------------- kernel 6: conv2 fp16 single-pass, 2 CTAs/SM ---------------
// SMEM (bytes):
//  A ring: 4 slots x 9216, px stride 144                        [0, 36864)
//  B: 46080 @36864  ([tap][kc][k16][n32*2B], 80B stride)
//  D: 3 planes x [n32][m64] f32 = 24576 @82944
#define C2_SMEM 107520
#define SM_A    0
#define SM_BH   36864
#define SM_D    82944

extern __shared__ unsigned char sm_c2[];

__global__ void __launch_bounds__(256, 2)
k_conv2m(const float* __restrict__ c2w, const float* __restrict__ c2b) {
    uint32_t sb = smem_u32(sm_c2);
    int tid  = threadIdx.x;
    int wrp  = tid >> 5;
    int lane = tid & 31;
    int mw = wrp >> 2;            // 0/1 : 32-px half
    int nw = wrp & 3;             // 0..3: 8-oc group
    int xt = blockIdx.x;          // 5 x-tiles of 62 out px
    int yt = blockIdx.y;          // 4 y-stripes of 64 rows
    int b   = blockIdx.z >> 1;
    int och = blockIdx.z & 1;
    int x0 = xt * 62;
    int y0 = yt * 64;
    int oc0 = och * 32;
    int npx = min(62, 256 - x0);

    // ---- stage weights (fp16): [tap][kc][k16][n32*2B], stride 80B
    for (int i = tid; i < 9*4*16*32; i += 256) {
        int n  = i & 31;
        int k  = (i >> 5) & 15;
        int kc = (i >> 9) & 3;
        int t  = i >> 11;
        int ic = kc*16 + k;
        float w = c2w[((size_t)(oc0 + n)*64 + ic)*9 + t];
        uint32_t off = SM_BH + (uint32_t)(((t*4 + kc)*16 + k)*80 + n*2);
        *reinterpret_cast<unsigned short*>(sm_c2 + off) = f2h(w);
    }

    // ---- cp.async row staging: 512 x 16B chunks, one commit group per row
    const uint4* f1h = reinterpret_cast<const uint4*>(g_f1h);
    auto stage_row = [&](int r) {
        int slot = (r + 600) % 4;
        uint32_t sbase = sb + SM_A + (uint32_t)slot * 9216u;
        bool inr = (r >= 0 && r < 256);
        size_t rowb = ((size_t)(b*65536 + (inr ? r : 0)*256))*8;
        #pragma unroll
        for (int it = 0; it < 2; it++) {
            int i = tid + it*256;
            int j  = (i >> 3) & 63;
            int c  = i & 7;
            int x = x0 - 1 + j;
            bool ok = inr && (x >= 0) && (x < 256);
            const uint4* sp = f1h + rowb
                            + (size_t)((x >= 0 && x < 256) ? x : 0)*8 + c;
            uint32_t daddr = sbase + (uint32_t)(j*144 + c*16);
            cp16(daddr, sp, ok ? 16 : 0);
        }
        CP_COMMIT();
    };

    stage_row(y0 - 1);
    stage_row(y0);
    stage_row(y0 + 1);
    __syncthreads();              // weights staged before first ldsm of B

    for (int y = y0; y < y0 + 64; y++) {
        stage_row(y + 2);
        CP_WAIT1();               // rows through y+1 resident
        __syncthreads();

        float acc[3][2][4];
        #pragma unroll
        for (int d = 0; d < 3; d++)
            #pragma unroll
            for (int m = 0; m < 2; m++)
                #pragma unroll
                for (int q = 0; q < 4; q++) acc[d][m][q] = 0.f;

        #pragma unroll
        for (int dy = 0; dy < 3; dy++) {
            int slot = (y - 1 + dy + 600) % 4;
            uint32_t abase = sb + SM_A + (uint32_t)slot*9216u;
            #pragma unroll
            for (int kc = 0; kc < 4; kc++) {
                uint32_t ah[2][4];
                #pragma unroll
                for (int mt = 0; mt < 2; mt++) {
                    uint32_t row = (uint32_t)(mw*32 + mt*16 + (lane & 15));
                    uint32_t aoff = row*144u + (uint32_t)((lane >> 4)*16 + kc*32);
                    ldsm_x4(ah[mt], abase + aoff);
                }
                #pragma unroll
                for (int dx = 0; dx < 3; dx++) {
                    int tap = dy*3 + dx;
                    uint32_t boff = (uint32_t)(((tap*4 + kc)*16 + (lane & 15))*80 + nw*16);
                    uint32_t bh[2];
                    ldsm_x2t(bh, sb + SM_BH + boff);
                    #pragma unroll
                    for (int mt = 0; mt < 2; mt++)
                        mma16816h(acc[dx][mt], ah[mt], bh);
                }
            }
        }

        // ---- write D planes [dx][n32][m64]
        float* sD = reinterpret_cast<float*>(sm_c2 + SM_D);
        #pragma unroll
        for (int dx = 0; dx < 3; dx++) {
            #pragma unroll
            for (int mt = 0; mt < 2; mt++) {
                int mbase = mw*32 + mt*16 + (lane >> 2);
                int nbase = nw*8 + (lane & 3)*2;
                sD[dx*2048 + (nbase    )*64 + mbase    ] = acc[dx][mt][0];
                sD[dx*2048 + (nbase + 1)*64 + mbase    ] = acc[dx][mt][1];
                sD[dx*2048 + (nbase    )*64 + mbase + 8] = acc[dx][mt][2];
                sD[dx*2048 + (nbase + 1)*64 + mbase + 8] = acc[dx][mt][3];
            }
        }
        __syncthreads();

        // ---- combine + store
        #pragma unroll
        for (int oo = 0; oo < 4; oo++) {
            int oc = wrp*4 + oo;
            float bias = c2b[oc0 + oc];
            float* dst = g_f2 + ((size_t)(b*64 + oc0 + oc))*65536 + y*256 + x0;
            #pragma unroll
            for (int pp = 0; pp < 64; pp += 32) {
                int p = lane + pp;
                if (p < npx) {
                    float v = sD[0*2048 + oc*64 + p]
                            + sD[1*2048 + oc*64 + p + 1]
                            + sD[2*2048 + oc*64 + p + 2] + bias;
                    dst[p] = fmaxf(v, 0.f);
                }
            }
        }
        __syncthreads();
    }
}

// ---------------- kernel 7: conv 5x5, 64->1, +bias ----------------
__global__ __launch_bounds__(256, 2)
void k_conv3(const float* __restrict__ c3w,
             const float* __restrict__ c3b,
             float* __restrict__ out) {
    __shared__ float sw[1600];
    __shared__ float sx[36*36];
    int b  = blockIdx.z;
    int x0 = blockIdx.x*32 - 2;
    int y0 = blockIdx.y*32 - 2;
    int tx = threadIdx.x & 31, ty = threadIdx.x >> 5;

    for (int idx = threadIdx.x; idx < 1600; idx += 256) sw[idx] = c3w[idx];

    float acc[4] = {0.f, 0.f, 0.f, 0.f};
    const float* f2b = g_f2 + (size_t)b*OC1*HU*WU;

    for (int ic = 0; ic < 64; ic++) {
        __syncthreads();
        const float* src = f2b + (size_t)ic*HU*WU;
        for (int idx = threadIdx.x; idx < 36*36; idx += 256) {
            int rr = idx / 36, cc = idx - rr*36;
            int gy = y0 + rr, gx = x0 + cc;
            sx[idx] = (gy >= 0 && gy < HU && gx >= 0 && gx < WU)
                      ? src[gy*WU + gx] : 0.f;
        }
        __syncthreads();

        #pragma unroll
        for (int dy = 0; dy < 5; dy++) {
            #pragma unroll
            for (int dx = 0; dx < 5; dx++) {
                float wv = sw[ic*25 + dy*5 + dx];
                #pragma unroll
                for (int k = 0; k < 4; k++)
                    acc[k] = fmaf(wv, sx[(ty*4 + k + dy)*36 + tx + dx], acc[k]);
            }
        }
    }

    float bias = c3b[0];
    #pragma unroll
    for (int k = 0; k < 4; k++) {
        int y = blockIdx.y*32 + ty*4 + k;
        int x = blockIdx.x*32 + tx;
        out[(size_t)b*HU*WU + y*WU + x] = acc[k] + bias;
    }
}

// ---------------- launch ----------------
extern "C" void kernel_launch(void* const* d_in, const int* in_sizes, int n_in,
                              void* d_out, int out_size) {
    (void)in_sizes; (void)n_in; (void)out_size;
    const float* img  = (const float*)d_in[0];
    const float* kern = (const float*)d_in[1];
    const float* kl_w = (const float*)d_in[2];
    const float* kl_b = (const float*)d_in[3];
    const float* w1_w = (const float*)d_in[4];
    const float* w1_b = (const float*)d_in[5];
    const float* c2_w = (const float*)d_in[6];
    const float* c2_b = (const float*)d_in[7];
    const float* c3_w = (const float*)d_in[8];
    const float* c3_b = (const float*)d_in[9];
    float* out = (float*)d_out;

    static int attr_set = 0;
    if (!attr_set) {
        cudaFuncSetAttribute(k_conv2m, cudaFuncAttributeMaxDynamicSharedMemorySize, C2_SMEM);
        attr_set = 1;
    }

    k_kfc  <<<BATCH, 256>>>(kern, kl_w, kl_b);
    k_w1   <<<W1OUT/64, 256>>>(w1_w, w1_b);
    k_up   <<<(BATCH*HU*WU)/256, 256>>>(img);
    k_conv1<<<dim3(8, 8, BATCH*8), 256>>>();
    k_conv2m<<<dim3(5, 4, BATCH*2), 256, C2_SMEM>>>(c2_w, c2_b);
    k_conv3<<<dim3(8, 8, BATCH), 256>>>(c3_w, c3_b, out);
}

// round 16
// speedup vs baseline: 1.1227x; 1.1227x over previous
#include <cuda_runtime.h>
#include <cuda_fp16.h>
#include <cstdint>

// ---------------- problem constants ----------------
#define BATCH 16
#define L2TAPS 225
#define FCDIM  2048
#define HIN 128
#define WIN 128
#define HU 256
#define WU 256
#define OC1 64
#define W1OUT (OC1*81)

// ---------------- device scratch ----------------
__device__ float g_kfc[BATCH*FCDIM];
__device__ float g_w1 [BATCH*W1OUT];
__device__ float g_up [BATCH*HU*WU];
__device__ unsigned short g_f1h[(size_t)BATCH*HU*WU*64];   // channels-last fp16
__device__ float g_f2 [(size_t)BATCH*OC1*HU*WU];           // planar f32

// ---------------- helpers ----------------
__device__ __forceinline__ uint32_t smem_u32(const void* p) {
    uint32_t a;
    asm("{ .reg .u64 t; cvta.to.shared.u64 t, %1; cvt.u32.u64 %0, t; }" : "=r"(a) : "l"(p));
    return a;
}
__device__ __forceinline__ unsigned short f2h(float v) {
    __half h = __float2half_rn(v);
    return *reinterpret_cast<unsigned short*>(&h);
}

__device__ __forceinline__ void ldsm_x4(uint32_t* r, uint32_t addr) {
    asm volatile("ldmatrix.sync.aligned.m8n8.x4.shared.b16 {%0,%1,%2,%3}, [%4];"
        : "=r"(r[0]), "=r"(r[1]), "=r"(r[2]), "=r"(r[3]) : "r"(addr));
}
__device__ __forceinline__ void ldsm_x2t(uint32_t* r, uint32_t addr) {
    asm volatile("ldmatrix.sync.aligned.m8n8.x2.trans.shared.b16 {%0,%1}, [%2];"
        : "=r"(r[0]), "=r"(r[1]) : "r"(addr));
}
__device__ __forceinline__ void ldsm_x4t(uint32_t* r, uint32_t addr) {
    asm volatile("ldmatrix.sync.aligned.m8n8.x4.trans.shared.b16 {%0,%1,%2,%3}, [%4];"
        : "=r"(r[0]), "=r"(r[1]), "=r"(r[2]), "=r"(r[3]) : "r"(addr));
}
__device__ __forceinline__ void mma16816h(float* c, const uint32_t* a, const uint32_t* b) {
    asm volatile("mma.sync.aligned.m16n8k16.row.col.f32.f16.f16.f32 "
        "{%0,%1,%2,%3}, {%4,%5,%6,%7}, {%8,%9}, {%0,%1,%2,%3};"
        : "+f"(c[0]), "+f"(c[1]), "+f"(c[2]), "+f"(c[3])
        : "r"(a[0]), "r"(a[1]), "r"(a[2]), "r"(a[3]), "r"(b[0]), "r"(b[1]));
}
__device__ __forceinline__ void cp16(uint32_t daddr, const void* src, int szbytes) {
    asm volatile("cp.async.cg.shared.global [%0], [%1], 16, %2;"
        :: "r"(daddr), "l"(src), "r"(szbytes) : "memory");
}
#define CP_COMMIT() asm volatile("cp.async.commit_group;" ::: "memory")
#define CP_WAIT2()  asm volatile("cp.async.wait_group 2;" ::: "memory")

// ---------------- kernel 1: kfc = relu(kflat @ kl_w^T + kl_b) ----------------
__global__ void k_kfc(const float* __restrict__ kern,
                      const float* __restrict__ kl_w,
                      const float* __restrict__ kl_b) {
    __shared__ float sk[L2TAPS];
    int b = blockIdx.x;
    for (int i = threadIdx.x; i < L2TAPS; i += blockDim.x)
        sk[i] = kern[b*L2TAPS + i];
    __syncthreads();
    for (int j = threadIdx.x; j < FCDIM; j += blockDim.x) {
        float acc = kl_b[j];
        const float* w = kl_w + (size_t)j*L2TAPS;
        #pragma unroll 5
        for (int i = 0; i < L2TAPS; i++) acc = fmaf(sk[i], w[i], acc);
        g_kfc[b*FCDIM + j] = fmaxf(acc, 0.0f);
    }
}

// ---------------- kernel 2: w1 = kfc @ w1_w^T + w1_b ----------------
__global__ void k_w1(const float* __restrict__ w1w,
                     const float* __restrict__ w1b) {
    __shared__ float sx[32*17];
    __shared__ float sw[32*65];
    int o0 = blockIdx.x * 64;
    int o  = threadIdx.x & 63;
    int bq = threadIdx.x >> 6;
    float acc[4] = {0.f, 0.f, 0.f, 0.f};
    for (int k0 = 0; k0 < FCDIM; k0 += 32) {
        for (int idx = threadIdx.x; idx < 64*32; idx += 256) {
            int ro = idx >> 5, ck = idx & 31;
            sw[ck*65 + ro] = w1w[(size_t)(o0 + ro)*FCDIM + k0 + ck];
        }
        for (int idx = threadIdx.x; idx < 16*32; idx += 256) {
            int rb = idx >> 5, ck = idx & 31;
            sx[ck*17 + rb] = g_kfc[rb*FCDIM + k0 + ck];
        }
        __syncthreads();
        #pragma unroll
        for (int k = 0; k < 32; k++) {
            float wv = sw[k*65 + o];
            acc[0] = fmaf(wv, sx[k*17 + bq     ], acc[0]);
            acc[1] = fmaf(wv, sx[k*17 + bq +  4], acc[1]);
            acc[2] = fmaf(wv, sx[k*17 + bq +  8], acc[2]);
            acc[3] = fmaf(wv, sx[k*17 + bq + 12], acc[3]);
        }
        __syncthreads();
    }
    float bias = w1b[o0 + o];
    #pragma unroll
    for (int i = 0; i < 4; i++)
        g_w1[(bq + 4*i)*W1OUT + o0 + o] = acc[i] + bias;
}

// ---------------- kernel 3: bilinear x2 upsample ----------------
__global__ void k_up(const float* __restrict__ img) {
    int idx = blockIdx.x*blockDim.x + threadIdx.x;
    if (idx >= BATCH*HU*WU) return;
    int x = idx & 255, y = (idx >> 8) & 255, b = idx >> 16;
    float syf = y*0.5f - 0.25f;
    float sxf = x*0.5f - 0.25f;
    int y0 = (int)floorf(syf); float wy = syf - (float)y0;
    int x0 = (int)floorf(sxf); float wx = sxf - (float)x0;
    int y0c = max(y0, 0), y1c = min(y0+1, HIN-1);
    int x0c = max(x0, 0), x1c = min(x0+1, WIN-1);
    const float* p = img + (size_t)b*HIN*WIN;
    float v00 = p[y0c*WIN + x0c], v01 = p[y0c*WIN + x1c];
    float v10 = p[y1c*WIN + x0c], v11 = p[y1c*WIN + x1c];
    g_up[idx] = (1.f-wy)*((1.f-wx)*v00 + wx*v01) + wy*((1.f-wx)*v10 + wx*v11);
}

// ---------------- kernel 5: conv1 via mma.sync (im2col GEMM) ----------------
// per block: one batch x 64-px x-tile x 16 rows.
// A: im2col [64 px][96 K] fp16, stride 208 B. B: w1 [96 K][64 oc], stride 144 B.
// 8 warps = 4 m16 tiles x 2 oc-halves (32 oc via 2 x ldsm_x4t).
#define C1_RING  (12*72)          // f32 ring: 12 rows x 72 cols
#define C1_ASZ   (64*208)         // 13312 B
#define C1_BSZ   (96*144)         // 13824 B

__global__ void __launch_bounds__(256, 2)
k_conv1m() {
    __shared__ float ring[C1_RING];
    __shared__ unsigned char As[C1_ASZ];
    __shared__ unsigned char Bs[C1_BSZ];

    int tid  = threadIdx.x;
    int wrp  = tid >> 5;
    int lane = tid & 31;
    int mw = wrp >> 1;            // 0..3 : m16 tile (16 px)
    int nw = wrp & 1;             // 0..1 : 32-oc half
    int xt = blockIdx.x;          // 4 x-tiles of 64 px
    int yt = blockIdx.y;          // 16 y-stripes of 16 rows
    int b  = blockIdx.z;
    int x0 = xt * 64;
    int y0 = yt * 16;

    uint32_t sbA = smem_u32(As);
    uint32_t sbB = smem_u32(Bs);

    // ---- zero B then stage w1 -> fp16 [t][oc], row stride 144 B
    for (int i = tid; i < C1_BSZ/4; i += 256)
        reinterpret_cast<uint32_t*>(Bs)[i] = 0u;
    // ---- zero A K-pad region: bytes 160..207 per row (taps 80..95; tap 80
    //      rewritten by the im2col build below). 160 is 4-aligned.
    for (int i = tid; i < 64*12; i += 256) {
        int j = i / 12, c = i % 12;
        *reinterpret_cast<uint32_t*>(As + j*208 + 160 + c*4) = 0u;
    }
    __syncthreads();
    for (int i = tid; i < 81*64; i += 256) {
        int oc = i & 63;
        int t  = i >> 6;
        float w = g_w1[b*W1OUT + oc*81 + t];
        *reinterpret_cast<unsigned short*>(Bs + t*144 + oc*2) = f2h(w);
    }

    // ---- stage initial ring rows y0-4 .. y0+3
    const float* up = g_up + (size_t)b*HU*WU;
    auto stage_ring = [&](int r) {
        if (tid < 72) {
            int xg = x0 - 4 + tid;
            float v = (r >= 0 && r < 256 && xg >= 0 && xg < 256)
                      ? up[r*256 + xg] : 0.f;
            ring[((r + 600) % 12)*72 + tid] = v;
        }
    };
    for (int r = y0 - 4; r <= y0 + 3; r++) stage_ring(r);
    __syncthreads();

    for (int y = y0; y < y0 + 16; y++) {
        stage_ring(y + 4);
        __syncthreads();

        // ---- build im2col A: 64 px x 81 taps
        for (int i = tid; i < 64*81; i += 256) {
            int j = i & 63;
            int t = i >> 6;
            int dy = t / 9, dx = t - dy*9;
            float v = ring[((y - 4 + dy + 600) % 12)*72 + j + dx];
            *reinterpret_cast<unsigned short*>(As + j*208 + t*2) = f2h(v);
        }
        __syncthreads();

        // ---- GEMM: M=16 (per warp), N=32 (per warp), K=96
        float acc[4][4];
        #pragma unroll
        for (int n = 0; n < 4; n++)
            #pragma unroll
            for (int q = 0; q < 4; q++) acc[n][q] = 0.f;

        #pragma unroll
        for (int kc = 0; kc < 6; kc++) {
            uint32_t ah[4];
            ldsm_x4(ah, sbA + (uint32_t)((mw*16 + (lane & 15))*208
                                         + (lane >> 4)*16 + kc*32));
            uint32_t bh[2][4];
            #pragma unroll
            for (int h = 0; h < 2; h++)
                ldsm_x4t(bh[h], sbB + (uint32_t)((kc*16 + (lane & 15))*144
                                                 + nw*64 + h*32 + (lane >> 4)*16));
            #pragma unroll
            for (int h = 0; h < 2; h++) {
                mma16816h(acc[h*2    ], ah, &bh[h][0]);
                mma16816h(acc[h*2 + 1], ah, &bh[h][2]);
            }
        }

        // ---- epilogue: relu + fp16, channels-last direct store
        #pragma unroll
        for (int n = 0; n < 4; n++) {
            int oc  = nw*32 + n*8 + (lane & 3)*2;
            int px0 = x0 + mw*16 + (lane >> 2);
            size_t base0 = ((size_t)(b*65536 + y*256 + px0))*64 + oc;
            size_t base1 = base0 + 8*64;
            uint32_t v0 = (uint32_t)f2h(fmaxf(acc[n][0], 0.f))
                        | ((uint32_t)f2h(fmaxf(acc[n][1], 0.f)) << 16);
            uint32_t v1 = (uint32_t)f2h(fmaxf(acc[n][2], 0.f))
                        | ((uint32_t)f2h(fmaxf(acc[n][3], 0.f)) << 16);
            *reinterpret_cast<uint32_t*>(g_f1h + base0) = v0;
            *reinterpret_cast<uint32_t*>(g_f1h + base1) = v1;
        }
        __syncthreads();
    }
}

// ---------------- kernel 6: conv2 fp16 single-pass (R13 config) -------------
// SMEM (bytes):
//  A ring: 6 slots x 9216, px stride 144                        [0, 55296)
//  B: 46080 @55296  ([tap][kc][k16][n32*2B], 80B stride)
//  D: 3 planes x [n32][m64] f32 = 24576 @101376
#define C2_SMEM 125952
#define SM_A    0
#define SM_BH   55296
#define SM_D    101376

extern __shared__ unsigned char sm_c2[];

__global__ void __launch_bounds__(256, 1)
k_conv2m(const float* __restrict__ c2w, const float* __restrict__ c2b) {
    uint32_t sb = smem_u32(sm_c2);
    int tid  = threadIdx.x;
    int wrp  = tid >> 5;
    int lane = tid & 31;
    int mw = wrp >> 2;            // 0/1 : 32-px half
    int nw = wrp & 3;             // 0..3: 8-oc group
    int xt = blockIdx.x;
    int yt = blockIdx.y;
    int b   = blockIdx.z >> 1;
    int och = blockIdx.z & 1;
    int x0 = xt * 62;
    int y0 = yt * 64;
    int oc0 = och * 32;
    int npx = min(62, 256 - x0);

    for (int i = tid; i < 9*4*16*32; i += 256) {
        int n  = i & 31;
        int k  = (i >> 5) & 15;
        int kc = (i >> 9) & 3;
        int t  = i >> 11;
        int ic = kc*16 + k;
        float w = c2w[((size_t)(oc0 + n)*64 + ic)*9 + t];
        uint32_t off = SM_BH + (uint32_t)(((t*4 + kc)*16 + k)*80 + n*2);
        *reinterpret_cast<unsigned short*>(sm_c2 + off) = f2h(w);
    }
    __syncthreads();

    uint32_t Bh[9][4][2];
    #pragma unroll
    for (int t = 0; t < 9; t++)
        #pragma unroll
        for (int kc = 0; kc < 4; kc++) {
            uint32_t boff = (uint32_t)(((t*4 + kc)*16 + (lane & 15))*80 + nw*16);
            ldsm_x2t(Bh[t][kc], sb + SM_BH + boff);
        }

    const uint4* f1h = reinterpret_cast<const uint4*>(g_f1h);
    auto stage_row = [&](int r) {
        int slot = (r + 600) % 6;
        uint32_t sbase = sb + SM_A + (uint32_t)slot * 9216u;
        bool inr = (r >= 0 && r < 256);
        size_t rowb = ((size_t)(b*65536 + (inr ? r : 0)*256))*8;
        #pragma unroll
        for (int it = 0; it < 2; it++) {
            int i = tid + it*256;
            int j  = (i >> 3) & 63;
            int c  = i & 7;
            int x = x0 - 1 + j;
            bool ok = inr && (x >= 0) && (x < 256);
            const uint4* sp = f1h + rowb
                            + (size_t)((x >= 0 && x < 256) ? x : 0)*8 + c;
            uint32_t daddr = sbase + (uint32_t)(j*144 + c*16);
            cp16(daddr, sp, ok ? 16 : 0);
        }
        CP_COMMIT();
    };

    stage_row(y0 - 1);
    stage_row(y0);
    stage_row(y0 + 1);
    stage_row(y0 + 2);

    for (int y = y0; y < y0 + 64; y++) {
        stage_row(y + 3);
        CP_WAIT2();
        __syncthreads();

        float acc[3][2][4];
        #pragma unroll
        for (int d = 0; d < 3; d++)
            #pragma unroll
            for (int m = 0; m < 2; m++)
                #pragma unroll
                for (int q = 0; q < 4; q++) acc[d][m][q] = 0.f;

        #pragma unroll
        for (int dy = 0; dy < 3; dy++) {
            int slot = (y - 1 + dy + 600) % 6;
            uint32_t abase = sb + SM_A + (uint32_t)slot*9216u;
            #pragma unroll
            for (int kc = 0; kc < 4; kc++) {
                uint32_t ah[2][4];
                #pragma unroll
                for (int mt = 0; mt < 2; mt++) {
                    uint32_t row = (uint32_t)(mw*32 + mt*16 + (lane & 15));
                    uint32_t aoff = row*144u + (uint32_t)((lane >> 4)*16 + kc*32);
                    ldsm_x4(ah[mt], abase + aoff);
                }
                #pragma unroll
                for (int dx = 0; dx < 3; dx++) {
                    int tap = dy*3 + dx;
                    #pragma unroll
                    for (int mt = 0; mt < 2; mt++)
                        mma16816h(acc[dx][mt], ah[mt], Bh[tap][kc]);
                }
            }
        }

        float* sD = reinterpret_cast<float*>(sm_c2 + SM_D);
        #pragma unroll
        for (int dx = 0; dx < 3; dx++) {
            #pragma unroll
            for (int mt = 0; mt < 2; mt++) {
                int mbase = mw*32 + mt*16 + (lane >> 2);
                int nbase = nw*8 + (lane & 3)*2;
                sD[dx*2048 + (nbase    )*64 + mbase    ] = acc[dx][mt][0];
                sD[dx*2048 + (nbase + 1)*64 + mbase    ] = acc[dx][mt][1];
                sD[dx*2048 + (nbase    )*64 + mbase + 8] = acc[dx][mt][2];
                sD[dx*2048 + (nbase + 1)*64 + mbase + 8] = acc[dx][mt][3];
            }
        }
        __syncthreads();

        #pragma unroll
        for (int oo = 0; oo < 4; oo++) {
            int oc = wrp*4 + oo;
            float bias = c2b[oc0 + oc];
            float* dst = g_f2 + ((size_t)(b*64 + oc0 + oc))*65536 + y*256 + x0;
            #pragma unroll
            for (int pp = 0; pp < 64; pp += 32) {
                int p = lane + pp;
                if (p < npx) {
                    float v = sD[0*2048 + oc*64 + p]
                            + sD[1*2048 + oc*64 + p + 1]
                            + sD[2*2048 + oc*64 + p + 2] + bias;
                    dst[p] = fmaxf(v, 0.f);
                }
            }
        }
        __syncthreads();
    }
}

// ---------------- kernel 7: conv 5x5, 64->1, +bias ----------------
__global__ __launch_bounds__(256, 2)
void k_conv3(const float* __restrict__ c3w,
             const float* __restrict__ c3b,
             float* __restrict__ out) {
    __shared__ float sw[1600];
    __shared__ float sx[36*36];
    int b  = blockIdx.z;
    int x0 = blockIdx.x*32 - 2;
    int y0 = blockIdx.y*32 - 2;
    int tx = threadIdx.x & 31, ty = threadIdx.x >> 5;

    for (int idx = threadIdx.x; idx < 1600; idx += 256) sw[idx] = c3w[idx];

    float acc[4] = {0.f, 0.f, 0.f, 0.f};
    const float* f2b = g_f2 + (size_t)b*OC1*HU*WU;

    for (int ic = 0; ic < 64; ic++) {
        __syncthreads();
        const float* src = f2b + (size_t)ic*HU*WU;
        for (int idx = threadIdx.x; idx < 36*36; idx += 256) {
            int rr = idx / 36, cc = idx - rr*36;
            int gy = y0 + rr, gx = x0 + cc;
            sx[idx] = (gy >= 0 && gy < HU && gx >= 0 && gx < WU)
                      ? src[gy*WU + gx] : 0.f;
        }
        __syncthreads();

        #pragma unroll
        for (int dy = 0; dy < 5; dy++) {
            #pragma unroll
            for (int dx = 0; dx < 5; dx++) {
                float wv = sw[ic*25 + dy*5 + dx];
                #pragma unroll
                for (int k = 0; k < 4; k++)
                    acc[k] = fmaf(wv, sx[(ty*4 + k + dy)*36 + tx + dx], acc[k]);
            }
        }
    }

    float bias = c3b[0];
    #pragma unroll
    for (int k = 0; k < 4; k++) {
        int y = blockIdx.y*32 + ty*4 + k;
        int x = blockIdx.x*32 + tx;
        out[(size_t)b*HU*WU + y*WU + x] = acc[k] + bias;
    }
}

// ---------------- launch ----------------
extern "C" void kernel_launch(void* const* d_in, const int* in_sizes, int n_in,
                              void* d_out, int out_size) {
    (void)in_sizes; (void)n_in; (void)out_size;
    const float* img  = (const float*)d_in[0];
    const float* kern = (const float*)d_in[1];
    const float* kl_w = (const float*)d_in[2];
    const float* kl_b = (const float*)d_in[3];
    const float* w1_w = (const float*)d_in[4];
    const float* w1_b = (const float*)d_in[5];
    const float* c2_w = (const float*)d_in[6];
    const float* c2_b = (const float*)d_in[7];
    const float* c3_w = (const float*)d_in[8];
    const float* c3_b = (const float*)d_in[9];
    float* out = (float*)d_out;

    static int attr_set = 0;
    if (!attr_set) {
        cudaFuncSetAttribute(k_conv2m, cudaFuncAttributeMaxDynamicSharedMemorySize, C2_SMEM);
        attr_set = 1;
    }

    k_kfc  <<<BATCH, 256>>>(kern, kl_w, kl_b);
    k_w1   <<<W1OUT/64, 256>>>(w1_w, w1_b);
    k_up   <<<(BATCH*HU*WU)/256, 256>>>(img);
    k_conv1m<<<dim3(4, 16, BATCH), 256>>>();
    k_conv2m<<<dim3(5, 4, BATCH*2), 256, C2_SMEM>>>(c2_w, c2_b);
    k_conv3<<<dim3(8, 8, BATCH), 256>>>(c3_w, c3_b, out);
}